// round 1
// baseline (speedup 1.0000x reference)
#include <cuda_runtime.h>
#include <cstdint>
#include <cstddef>

#define BTILE    32
#define S_LEN    256
#define F_IN     5
#define HID      64
#define GATES    256
#define NTHREADS 256

typedef unsigned long long ull;

// ---------- packed f32x2 helpers (Blackwell sm_100a) ----------
__device__ __forceinline__ ull pk2(float a, float b) {
    ull r;
    asm("mov.b64 %0, {%1, %2};" : "=l"(r) : "r"(__float_as_uint(a)), "r"(__float_as_uint(b)));
    return r;
}
__device__ __forceinline__ ull dup2(float a) {
    ull r;
    asm("mov.b64 %0, {%1, %1};" : "=l"(r) : "r"(__float_as_uint(a)));
    return r;
}
__device__ __forceinline__ void unpk(ull v, float& a, float& b) {
    unsigned int lo, hi;
    asm("mov.b64 {%0, %1}, %2;" : "=r"(lo), "=r"(hi) : "l"(v));
    a = __uint_as_float(lo);
    b = __uint_as_float(hi);
}
__device__ __forceinline__ void fma2(ull& d, ull a, ull b) {
    asm("fma.rn.f32x2 %0, %1, %2, %0;" : "+l"(d) : "l"(a), "l"(b));
}

// ---------- fast-but-accurate transcendentals (ex2-based, ~1e-6 rel) ----------
__device__ __forceinline__ float sigm(float x) {
    return __fdividef(1.0f, 1.0f + __expf(-x));
}
__device__ __forceinline__ float tanh_(float x) {
    return __fdividef(2.0f, 1.0f + __expf(-2.0f * x)) - 1.0f;
}

// gate permutation: g = m*64 + j  ->  p = (j>>1)*8 + m*2 + (j&1)
// so thread tg (j in {2tg, 2tg+1}) holds i,f,g,o for its two cells contiguously.
__device__ __forceinline__ int permg(int g) {
    int j = g & 63;
    int m = g >> 6;
    return ((j >> 1) << 3) + (m << 1) + (j & 1);
}

// acc[bb][u]: bb = batch 0..3, u = gate-kind 0..3 (i,f,g,o), each a f32x2 pair (cells 2tg,2tg+1)
__device__ __forceinline__ void gemm64(const float* __restrict__ hsrc,
                                       const float* __restrict__ Wsm,
                                       int tg, int b0, ull acc[4][4]) {
    const float* wp = Wsm + tg * 8;
    #pragma unroll 1
    for (int k4 = 0; k4 < HID; k4 += 4) {
        float hf[4][4];
        #pragma unroll
        for (int bb = 0; bb < 4; bb++) {
            float4 v = *(const float4*)(hsrc + (b0 + bb) * HID + k4);
            hf[bb][0] = v.x; hf[bb][1] = v.y; hf[bb][2] = v.z; hf[bb][3] = v.w;
        }
        #pragma unroll
        for (int kk = 0; kk < 4; kk++) {
            float4 wa = *(const float4*)(wp + (k4 + kk) * GATES);
            float4 wb = *(const float4*)(wp + (k4 + kk) * GATES + 4);
            ull w0 = pk2(wa.x, wa.y), w1 = pk2(wa.z, wa.w);
            ull w2 = pk2(wb.x, wb.y), w3 = pk2(wb.z, wb.w);
            #pragma unroll
            for (int bb = 0; bb < 4; bb++) {
                ull hv = dup2(hf[bb][kk]);
                fma2(acc[bb][0], w0, hv);
                fma2(acc[bb][1], w1, hv);
                fma2(acc[bb][2], w2, hv);
                fma2(acc[bb][3], w3, hv);
            }
        }
    }
}

__device__ __forceinline__ float mlp_head(const float* __restrict__ hb,
                                          const float* __restrict__ w1,
                                          const float* __restrict__ b1,
                                          const float* __restrict__ w2,
                                          const float* __restrict__ b2) {
    float acc = b2[0];
    #pragma unroll 4
    for (int u = 0; u < 16; u++) {
        float s = b1[u];
        #pragma unroll 8
        for (int k = 0; k < HID; k++) s += hb[k] * w1[u * HID + k];
        acc += fmaxf(s, 0.0f) * w2[u];
    }
    return sigm(acc);
}

__global__ void __launch_bounds__(NTHREADS, 1)
lstm_behavior_kernel(const float* __restrict__ x,
                     const float* __restrict__ w_ih0, const float* __restrict__ w_hh0,
                     const float* __restrict__ b_ih0, const float* __restrict__ b_hh0,
                     const float* __restrict__ w_ih1, const float* __restrict__ w_hh1,
                     const float* __restrict__ b_ih1, const float* __restrict__ b_hh1,
                     const float* __restrict__ eng_w1, const float* __restrict__ eng_b1,
                     const float* __restrict__ eng_w2, const float* __restrict__ eng_b2,
                     const float* __restrict__ prop_w1, const float* __restrict__ prop_b1,
                     const float* __restrict__ prop_w2, const float* __restrict__ prop_b2,
                     const float* __restrict__ seg_w, const float* __restrict__ seg_b,
                     float* __restrict__ out, int Btot) {
    extern __shared__ float smf[];
    float* W0  = smf;                       // [64][256] w_hh0, k-major, gate-permuted
    float* W1i = W0  + HID * GATES;         // [64][256] w_ih1
    float* W1h = W1i + HID * GATES;         // [64][256] w_hh1
    float* WX  = W1h + HID * GATES;         // [5][256]  w_ih0, f-major, gate-permuted
    float* B0  = WX  + F_IN * GATES;        // [256] b_ih0 + b_hh0 (permuted)
    float* B1  = B0  + GATES;               // [256]
    float* HA  = B1  + GATES;               // [32][64] layer0 h state
    float* HB  = HA  + BTILE * HID;         // [32][64] layer1 h state
    float* XS  = HB  + BTILE * HID;         // [32][5]  x staging for current step

    const int tid = threadIdx.x;

    // ---- prologue: load + permute weights into SMEM ----
    for (int idx = tid; idx < HID * GATES; idx += NTHREADS) {
        int g = idx >> 6, k = idx & 63;
        int p = permg(g);
        W0 [k * GATES + p] = w_hh0[idx];
        W1i[k * GATES + p] = w_ih1[idx];
        W1h[k * GATES + p] = w_hh1[idx];
    }
    for (int idx = tid; idx < GATES * F_IN; idx += NTHREADS) {
        int g = idx / F_IN, f = idx - g * F_IN;
        WX[f * GATES + permg(g)] = w_ih0[idx];
    }
    if (tid < GATES) {
        int p = permg(tid);
        B0[p] = b_ih0[tid] + b_hh0[tid];
        B1[p] = b_ih1[tid] + b_hh1[tid];
    }
    for (int idx = tid; idx < BTILE * HID; idx += NTHREADS) {
        HA[idx] = 0.0f;
        HB[idx] = 0.0f;
    }
    __syncthreads();

    const int tg = tid & 31;      // gate-group: cells j = 2tg, 2tg+1
    const int tb = tid >> 5;      // batch-group
    const int b0 = tb * 4;
    const float* xblk = x + (size_t)blockIdx.x * BTILE * (S_LEN * F_IN);

    float cA[4][2], cB[4][2];
    #pragma unroll
    for (int bb = 0; bb < 4; bb++) {
        cA[bb][0] = 0.0f; cA[bb][1] = 0.0f;
        cB[bb][0] = 0.0f; cB[bb][1] = 0.0f;
    }

    for (int t = 0; t < S_LEN; ++t) {
        // stage this step's x slice (32 batches x 5 features)
        if (tid < BTILE * F_IN) {
            int b = tid / F_IN, f = tid - b * F_IN;
            XS[tid] = xblk[b * (S_LEN * F_IN) + t * F_IN + f];
        }
        __syncthreads();   // XS ready; HB(t-1) write visible

        // ===== layer 0: gates = B0 + x*W_ih0 + hA*W_hh0 =====
        ull acc[4][4];
        #pragma unroll
        for (int u = 0; u < 4; u++) {
            float2 bv = *(const float2*)(B0 + tg * 8 + 2 * u);
            ull a = pk2(bv.x, bv.y);
            acc[0][u] = a; acc[1][u] = a; acc[2][u] = a; acc[3][u] = a;
        }
        #pragma unroll
        for (int f = 0; f < F_IN; ++f) {
            float4 wa = *(const float4*)(WX + f * GATES + tg * 8);
            float4 wb = *(const float4*)(WX + f * GATES + tg * 8 + 4);
            ull w0 = pk2(wa.x, wa.y), w1 = pk2(wa.z, wa.w);
            ull w2 = pk2(wb.x, wb.y), w3 = pk2(wb.z, wb.w);
            #pragma unroll
            for (int bb = 0; bb < 4; bb++) {
                ull xv = dup2(XS[(b0 + bb) * F_IN + f]);
                fma2(acc[bb][0], w0, xv); fma2(acc[bb][1], w1, xv);
                fma2(acc[bb][2], w2, xv); fma2(acc[bb][3], w3, xv);
            }
        }
        gemm64(HA, W0, tg, b0, acc);

        float hAn[4][2];
        #pragma unroll
        for (int bb = 0; bb < 4; bb++) {
            float i0, i1, f0, f1, g0, g1, o0, o1;
            unpk(acc[bb][0], i0, i1);
            unpk(acc[bb][1], f0, f1);
            unpk(acc[bb][2], g0, g1);
            unpk(acc[bb][3], o0, o1);
            float c0 = sigm(f0) * cA[bb][0] + sigm(i0) * tanh_(g0);
            float c1 = sigm(f1) * cA[bb][1] + sigm(i1) * tanh_(g1);
            cA[bb][0] = c0; cA[bb][1] = c1;
            hAn[bb][0] = sigm(o0) * tanh_(c0);
            hAn[bb][1] = sigm(o1) * tanh_(c1);
        }
        __syncthreads();   // everyone done reading HA(t-1)
        #pragma unroll
        for (int bb = 0; bb < 4; bb++)
            *(float2*)(HA + (b0 + bb) * HID + tg * 2) = make_float2(hAn[bb][0], hAn[bb][1]);
        __syncthreads();   // HA(t) visible

        // ===== layer 1: gates = B1 + hA(t)*W_ih1 + hB(t-1)*W_hh1 =====
        #pragma unroll
        for (int u = 0; u < 4; u++) {
            float2 bv = *(const float2*)(B1 + tg * 8 + 2 * u);
            ull a = pk2(bv.x, bv.y);
            acc[0][u] = a; acc[1][u] = a; acc[2][u] = a; acc[3][u] = a;
        }
        gemm64(HA, W1i, tg, b0, acc);
        gemm64(HB, W1h, tg, b0, acc);

        float hBn[4][2];
        #pragma unroll
        for (int bb = 0; bb < 4; bb++) {
            float i0, i1, f0, f1, g0, g1, o0, o1;
            unpk(acc[bb][0], i0, i1);
            unpk(acc[bb][1], f0, f1);
            unpk(acc[bb][2], g0, g1);
            unpk(acc[bb][3], o0, o1);
            float c0 = sigm(f0) * cB[bb][0] + sigm(i0) * tanh_(g0);
            float c1 = sigm(f1) * cB[bb][1] + sigm(i1) * tanh_(g1);
            cB[bb][0] = c0; cB[bb][1] = c1;
            hBn[bb][0] = sigm(o0) * tanh_(c0);
            hBn[bb][1] = sigm(o1) * tanh_(c1);
        }
        __syncthreads();   // everyone done reading HB(t-1)
        #pragma unroll
        for (int bb = 0; bb < 4; bb++)
            *(float2*)(HB + (b0 + bb) * HID + tg * 2) = make_float2(hBn[bb][0], hBn[bb][1]);
        // HB(t) visibility covered by next iteration's first barrier
    }
    __syncthreads();

    // ---- heads: one thread per batch element of this tile ----
    if (tid < BTILE) {
        const float* hb = HB + tid * HID;
        int b = blockIdx.x * BTILE + tid;
        out[b]        = mlp_head(hb, eng_w1, eng_b1, eng_w2, eng_b2);
        out[Btot + b] = mlp_head(hb, prop_w1, prop_b1, prop_w2, prop_b2);
        #pragma unroll
        for (int j = 0; j < 5; j++) {
            float s = seg_b[j];
            #pragma unroll 8
            for (int k = 0; k < HID; k++) s += hb[k] * seg_w[j * HID + k];
            out[2 * Btot + b * 5 + j] = s;
        }
    }
}

extern "C" void kernel_launch(void* const* d_in, const int* in_sizes, int n_in,
                              void* d_out, int out_size) {
    const float* x       = (const float*)d_in[0];
    const float* w_ih0   = (const float*)d_in[1];
    const float* w_hh0   = (const float*)d_in[2];
    const float* b_ih0   = (const float*)d_in[3];
    const float* b_hh0   = (const float*)d_in[4];
    const float* w_ih1   = (const float*)d_in[5];
    const float* w_hh1   = (const float*)d_in[6];
    const float* b_ih1   = (const float*)d_in[7];
    const float* b_hh1   = (const float*)d_in[8];
    const float* eng_w1  = (const float*)d_in[9];
    const float* eng_b1  = (const float*)d_in[10];
    const float* eng_w2  = (const float*)d_in[11];
    const float* eng_b2  = (const float*)d_in[12];
    const float* prop_w1 = (const float*)d_in[13];
    const float* prop_b1 = (const float*)d_in[14];
    const float* prop_w2 = (const float*)d_in[15];
    const float* prop_b2 = (const float*)d_in[16];
    const float* seg_w   = (const float*)d_in[17];
    const float* seg_b   = (const float*)d_in[18];
    float* out = (float*)d_out;

    int Btot = in_sizes[0] / (S_LEN * F_IN);   // 4096
    int grid = Btot / BTILE;                   // 128

    size_t smem = (size_t)(3 * HID * GATES + F_IN * GATES + 2 * GATES +
                           2 * BTILE * HID + BTILE * F_IN) * sizeof(float); // 220,800 B
    cudaFuncSetAttribute(lstm_behavior_kernel,
                         cudaFuncAttributeMaxDynamicSharedMemorySize, (int)smem);

    lstm_behavior_kernel<<<grid, NTHREADS, smem>>>(
        x, w_ih0, w_hh0, b_ih0, b_hh0, w_ih1, w_hh1, b_ih1, b_hh1,
        eng_w1, eng_b1, eng_w2, eng_b2, prop_w1, prop_b1, prop_w2, prop_b2,
        seg_w, seg_b, out, Btot);
}

// round 2
// speedup vs baseline: 1.6464x; 1.6464x over previous
#include <cuda_runtime.h>
#include <cstdint>
#include <cstddef>

#define BTILE    32
#define S_LEN    256
#define F_IN     5
#define HID      64
#define GATES    256
#define NTHREADS 256

typedef unsigned long long ull;

// ---------- packed f32x2 helpers (sm_100a) ----------
__device__ __forceinline__ ull pk2(float a, float b) {
    ull r;
    asm("mov.b64 %0, {%1, %2};" : "=l"(r) : "r"(__float_as_uint(a)), "r"(__float_as_uint(b)));
    return r;
}
__device__ __forceinline__ ull dup2(float a) {
    ull r;
    asm("mov.b64 %0, {%1, %1};" : "=l"(r) : "r"(__float_as_uint(a)));
    return r;
}
__device__ __forceinline__ void unpk(ull v, float& a, float& b) {
    unsigned int lo, hi;
    asm("mov.b64 {%0, %1}, %2;" : "=r"(lo), "=r"(hi) : "l"(v));
    a = __uint_as_float(lo);
    b = __uint_as_float(hi);
}
__device__ __forceinline__ void fma2(ull& d, ull a, ull b) {
    asm("fma.rn.f32x2 %0, %1, %2, %0;" : "+l"(d) : "l"(a), "l"(b));
}

#define BARP(id) asm volatile("bar.sync %0, 64;" :: "r"(id) : "memory")

// ---------- transcendentals (ex2-based, ~1e-6 rel) ----------
__device__ __forceinline__ float sigm(float x) {
    return __fdividef(1.0f, 1.0f + __expf(-x));
}
__device__ __forceinline__ float tanh_(float x) {
    return __fdividef(2.0f, 1.0f + __expf(-2.0f * x)) - 1.0f;
}

// gate permutation: g = m*64 + cell  ->  p = cell*4 + m
// thread owning cell c loads its 4 gate weights as one float4 at W[k][c*4].
__device__ __forceinline__ int permg(int g) {
    return ((g & 63) << 2) + (g >> 6);
}

// cell update: aif = (i,f) preact pair, ago = (g,o) pair
__device__ __forceinline__ float cell_update(ull aif, ull ago, float& c) {
    float iv, fv, gv, ov;
    unpk(aif, iv, fv);
    unpk(ago, gv, ov);
    float cn = sigm(fv) * c + sigm(iv) * tanh_(gv);
    c = cn;
    return sigm(ov) * tanh_(cn);
}

// acc[b][0] = (i,f) pair, acc[b][1] = (g,o) pair for cell C, batches b0..b0+7
__device__ __forceinline__ void gemm64(const float* __restrict__ hsrc,
                                       const float* __restrict__ Wsm,
                                       int C, int b0, ull acc[8][2]) {
    const float* wp = Wsm + C * 4;
    #pragma unroll 2
    for (int k4 = 0; k4 < HID; k4 += 4) {
        float4 h4[8];
        #pragma unroll
        for (int b = 0; b < 8; b++)
            h4[b] = *(const float4*)(hsrc + (b0 + b) * HID + k4);
        #pragma unroll
        for (int kk = 0; kk < 4; kk++) {
            float4 wv = *(const float4*)(wp + (k4 + kk) * GATES);
            ull wif = pk2(wv.x, wv.y);
            ull wgo = pk2(wv.z, wv.w);
            #pragma unroll
            for (int b = 0; b < 8; b++) {
                float hs = (kk == 0) ? h4[b].x : (kk == 1) ? h4[b].y
                         : (kk == 2) ? h4[b].z : h4[b].w;
                ull hv = dup2(hs);
                fma2(acc[b][0], wif, hv);
                fma2(acc[b][1], wgo, hv);
            }
        }
    }
}

__device__ __forceinline__ float mlp_head(const float* __restrict__ hb,
                                          const float* __restrict__ w1,
                                          const float* __restrict__ b1,
                                          const float* __restrict__ w2,
                                          const float* __restrict__ b2) {
    float acc = b2[0];
    #pragma unroll 4
    for (int u = 0; u < 16; u++) {
        float s = b1[u];
        #pragma unroll 8
        for (int k = 0; k < HID; k++) s += hb[k] * w1[u * HID + k];
        acc += fmaxf(s, 0.0f) * w2[u];
    }
    return sigm(acc);
}

__global__ void __launch_bounds__(NTHREADS, 1)
lstm_behavior_kernel(const float* __restrict__ x,
                     const float* __restrict__ w_ih0, const float* __restrict__ w_hh0,
                     const float* __restrict__ b_ih0, const float* __restrict__ b_hh0,
                     const float* __restrict__ w_ih1, const float* __restrict__ w_hh1,
                     const float* __restrict__ b_ih1, const float* __restrict__ b_hh1,
                     const float* __restrict__ eng_w1, const float* __restrict__ eng_b1,
                     const float* __restrict__ eng_w2, const float* __restrict__ eng_b2,
                     const float* __restrict__ prop_w1, const float* __restrict__ prop_b1,
                     const float* __restrict__ prop_w2, const float* __restrict__ prop_b2,
                     const float* __restrict__ seg_w, const float* __restrict__ seg_b,
                     float* __restrict__ out, int Btot) {
    extern __shared__ float smf[];
    float* W0  = smf;                       // [64][256] w_hh0, k-major, permuted
    float* W1i = W0  + HID * GATES;         // [64][256] w_ih1
    float* W1h = W1i + HID * GATES;         // [64][256] w_hh1
    float* WX  = W1h + HID * GATES;         // [5][256]  w_ih0, f-major, permuted
    float* B0  = WX  + F_IN * GATES;        // [256] b_ih0 + b_hh0 (permuted)
    float* B1  = B0  + GATES;               // [256]
    float* HA  = B1  + GATES;               // [32][64] layer0 h
    float* HB  = HA  + BTILE * HID;         // [32][64] layer1 h
    float* XS  = HB  + BTILE * HID;         // [4][40]  x staging

    const int tid = threadIdx.x;

    // ---- prologue: load + permute weights into SMEM ----
    for (int idx = tid; idx < HID * GATES; idx += NTHREADS) {
        int g = idx >> 6, k = idx & 63;
        int p = permg(g);
        W0 [k * GATES + p] = w_hh0[idx];
        W1i[k * GATES + p] = w_ih1[idx];
        W1h[k * GATES + p] = w_hh1[idx];
    }
    for (int idx = tid; idx < GATES * F_IN; idx += NTHREADS) {
        int g = idx / F_IN, f = idx - g * F_IN;
        WX[f * GATES + permg(g)] = w_ih0[idx];
    }
    if (tid < GATES) {
        int p = permg(tid);
        B0[p] = b_ih0[tid] + b_hh0[tid];
        B1[p] = b_ih1[tid] + b_hh1[tid];
    }
    for (int idx = tid; idx < BTILE * HID; idx += NTHREADS) {
        HA[idx] = 0.0f;
        HB[idx] = 0.0f;
    }
    __syncthreads();

    const int w    = tid >> 5;
    const int lane = tid & 31;
    const int bg   = w >> 1;          // batch group (8 batches)
    const int ch   = w & 1;           // cell half
    const int C    = ch * 32 + lane;  // my cell 0..63
    const int b0   = bg * 8;
    const int plid = ch * 32 + lane;  // pair-local thread id 0..63
    const int barid = bg + 1;         // named barrier per pair (ids 1..4)

    const bool xload = (plid < BTILE * F_IN / 4);  // plid < 40
    const int  xb = plid / F_IN, xf = plid - xb * F_IN;
    const float* xrow = x + (size_t)(blockIdx.x * BTILE + b0 + xb) * (S_LEN * F_IN) + xf;
    float* xs_mine = XS + bg * 40 + plid;
    const float* xs_base = XS + bg * 40;

    float cA[8], cB[8];
    #pragma unroll
    for (int b = 0; b < 8; b++) { cA[b] = 0.0f; cB[b] = 0.0f; }

    float xreg = xload ? xrow[0] : 0.0f;   // prefetch t=0

    for (int t = 0; t < S_LEN; ++t) {
        if (xload) *xs_mine = xreg;
        BARP(barid);                         // XS(t), HB(t-1) visible to pair

        if (t + 1 < S_LEN && xload)
            xreg = xrow[(t + 1) * F_IN];     // prefetch next step (hidden under compute)

        // ===== layer 0: gates = B0 + x*W_ih0 + hA(t-1)*W_hh0 =====
        ull acc[8][2];
        {
            float4 bv = *(const float4*)(B0 + C * 4);
            ull bif = pk2(bv.x, bv.y), bgo = pk2(bv.z, bv.w);
            #pragma unroll
            for (int b = 0; b < 8; b++) { acc[b][0] = bif; acc[b][1] = bgo; }
        }
        #pragma unroll
        for (int f = 0; f < F_IN; ++f) {
            float4 wv = *(const float4*)(WX + f * GATES + C * 4);
            ull wif = pk2(wv.x, wv.y), wgo = pk2(wv.z, wv.w);
            #pragma unroll
            for (int b = 0; b < 8; b++) {
                ull xv = dup2(xs_base[b * F_IN + f]);
                fma2(acc[b][0], wif, xv);
                fma2(acc[b][1], wgo, xv);
            }
        }
        gemm64(HA, W0, C, b0, acc);

        float hn[8];
        #pragma unroll
        for (int b = 0; b < 8; b++)
            hn[b] = cell_update(acc[b][0], acc[b][1], cA[b]);

        BARP(barid);                         // pair done reading HA(t-1)
        #pragma unroll
        for (int b = 0; b < 8; b++)
            HA[(b0 + b) * HID + C] = hn[b];
        BARP(barid);                         // HA(t) visible to pair

        // ===== layer 1: gates = B1 + hA(t)*W_ih1 + hB(t-1)*W_hh1 =====
        {
            float4 bv = *(const float4*)(B1 + C * 4);
            ull bif = pk2(bv.x, bv.y), bgo = pk2(bv.z, bv.w);
            #pragma unroll
            for (int b = 0; b < 8; b++) { acc[b][0] = bif; acc[b][1] = bgo; }
        }
        gemm64(HA, W1i, C, b0, acc);
        gemm64(HB, W1h, C, b0, acc);

        #pragma unroll
        for (int b = 0; b < 8; b++)
            hn[b] = cell_update(acc[b][0], acc[b][1], cB[b]);

        BARP(barid);                         // pair done reading HB(t-1)
        #pragma unroll
        for (int b = 0; b < 8; b++)
            HB[(b0 + b) * HID + C] = hn[b];
        // HB(t) visibility: next iteration's first BARP
    }
    __syncthreads();   // all pairs' final HB visible block-wide

    // ---- heads: one thread per batch element of this tile ----
    if (tid < BTILE) {
        const float* hb = HB + tid * HID;
        int b = blockIdx.x * BTILE + tid;
        out[b]        = mlp_head(hb, eng_w1, eng_b1, eng_w2, eng_b2);
        out[Btot + b] = mlp_head(hb, prop_w1, prop_b1, prop_w2, prop_b2);
        #pragma unroll
        for (int j = 0; j < 5; j++) {
            float s = seg_b[j];
            #pragma unroll 8
            for (int k = 0; k < HID; k++) s += hb[k] * seg_w[j * HID + k];
            out[2 * Btot + b * 5 + j] = s;
        }
    }
}

extern "C" void kernel_launch(void* const* d_in, const int* in_sizes, int n_in,
                              void* d_out, int out_size) {
    const float* x       = (const float*)d_in[0];
    const float* w_ih0   = (const float*)d_in[1];
    const float* w_hh0   = (const float*)d_in[2];
    const float* b_ih0   = (const float*)d_in[3];
    const float* b_hh0   = (const float*)d_in[4];
    const float* w_ih1   = (const float*)d_in[5];
    const float* w_hh1   = (const float*)d_in[6];
    const float* b_ih1   = (const float*)d_in[7];
    const float* b_hh1   = (const float*)d_in[8];
    const float* eng_w1  = (const float*)d_in[9];
    const float* eng_b1  = (const float*)d_in[10];
    const float* eng_w2  = (const float*)d_in[11];
    const float* eng_b2  = (const float*)d_in[12];
    const float* prop_w1 = (const float*)d_in[13];
    const float* prop_b1 = (const float*)d_in[14];
    const float* prop_w2 = (const float*)d_in[15];
    const float* prop_b2 = (const float*)d_in[16];
    const float* seg_w   = (const float*)d_in[17];
    const float* seg_b   = (const float*)d_in[18];
    float* out = (float*)d_out;

    int Btot = in_sizes[0] / (S_LEN * F_IN);   // 4096
    int grid = Btot / BTILE;                   // 128

    size_t smem = (size_t)(3 * HID * GATES + F_IN * GATES + 2 * GATES +
                           2 * BTILE * HID + 4 * 40) * sizeof(float); // 220,800 B
    cudaFuncSetAttribute(lstm_behavior_kernel,
                         cudaFuncAttributeMaxDynamicSharedMemorySize, (int)smem);

    lstm_behavior_kernel<<<grid, NTHREADS, smem>>>(
        x, w_ih0, w_hh0, b_ih0, b_hh0, w_ih1, w_hh1, b_ih1, b_hh1,
        eng_w1, eng_b1, eng_w2, eng_b2, prop_w1, prop_b1, prop_w2, prop_b2,
        seg_w, seg_b, out, Btot);
}

// round 3
// speedup vs baseline: 1.9329x; 1.1740x over previous
#include <cuda_runtime.h>
#include <cstdint>
#include <cstddef>

#define BTILE    28      // batches per CTA (grid 147 covers 148 SMs in one wave)
#define GPB      4       // batch groups per block
#define BPG      7       // batches per group
#define S_LEN    256
#define F_IN     5
#define HID      64
#define GATES    256
#define NTHREADS 256

typedef unsigned long long ull;

// ---------- packed f32x2 helpers (sm_100a) ----------
__device__ __forceinline__ ull pk2(float a, float b) {
    ull r;
    asm("mov.b64 %0, {%1, %2};" : "=l"(r) : "r"(__float_as_uint(a)), "r"(__float_as_uint(b)));
    return r;
}
__device__ __forceinline__ ull dup2(float a) {
    ull r;
    asm("mov.b64 %0, {%1, %1};" : "=l"(r) : "r"(__float_as_uint(a)));
    return r;
}
__device__ __forceinline__ void unpk(ull v, float& a, float& b) {
    unsigned int lo, hi;
    asm("mov.b64 {%0, %1}, %2;" : "=r"(lo), "=r"(hi) : "l"(v));
    a = __uint_as_float(lo);
    b = __uint_as_float(hi);
}
__device__ __forceinline__ void fma2(ull& d, ull a, ull b) {
    asm("fma.rn.f32x2 %0, %1, %2, %0;" : "+l"(d) : "l"(a), "l"(b));
}

#define BARP(id) asm volatile("bar.sync %0, 64;" :: "r"(id) : "memory")

// ---------- transcendentals (ex2-based, ~1e-6 rel) ----------
__device__ __forceinline__ float sigm(float x) {
    return __fdividef(1.0f, 1.0f + __expf(-x));
}
__device__ __forceinline__ float tanh_(float x) {
    return __fdividef(2.0f, 1.0f + __expf(-2.0f * x)) - 1.0f;
}

// gate permutation: g = m*64 + cell  ->  p = cell*4 + m
__device__ __forceinline__ int permg(int g) {
    return ((g & 63) << 2) + (g >> 6);
}

__device__ __forceinline__ float cell_update(ull aif, ull ago, float& c) {
    float iv, fv, gv, ov;
    unpk(aif, iv, fv);
    unpk(ago, gv, ov);
    float cn = sigm(fv) * c + sigm(iv) * tanh_(gv);
    c = cn;
    return sigm(ov) * tanh_(cn);
}

// acc[b][0]=(i,f), acc[b][1]=(g,o) for cell C, batches b0..b0+6
__device__ __forceinline__ void gemm7(const float* __restrict__ hsrc,
                                      const float* __restrict__ Wsm,
                                      int C, int b0, ull acc[BPG][2]) {
    const float* wp = Wsm + C * 4;
    #pragma unroll 4
    for (int k4 = 0; k4 < HID; k4 += 4) {
        float4 h4[BPG];
        #pragma unroll
        for (int b = 0; b < BPG; b++)
            h4[b] = *(const float4*)(hsrc + (b0 + b) * HID + k4);
        #pragma unroll
        for (int kk = 0; kk < 4; kk++) {
            float4 wv = *(const float4*)(wp + (k4 + kk) * GATES);
            ull wif = pk2(wv.x, wv.y);
            ull wgo = pk2(wv.z, wv.w);
            #pragma unroll
            for (int b = 0; b < BPG; b++) {
                float hs = (kk == 0) ? h4[b].x : (kk == 1) ? h4[b].y
                         : (kk == 2) ? h4[b].z : h4[b].w;
                ull hv = dup2(hs);
                fma2(acc[b][0], wif, hv);
                fma2(acc[b][1], wgo, hv);
            }
        }
    }
}

__device__ __forceinline__ float mlp_head(const float* __restrict__ hb,
                                          const float* __restrict__ w1,
                                          const float* __restrict__ b1,
                                          const float* __restrict__ w2,
                                          const float* __restrict__ b2) {
    float acc = b2[0];
    #pragma unroll 4
    for (int u = 0; u < 16; u++) {
        float s = b1[u];
        #pragma unroll 8
        for (int k = 0; k < HID; k++) s += hb[k] * w1[u * HID + k];
        acc += fmaxf(s, 0.0f) * w2[u];
    }
    return sigm(acc);
}

__global__ void __launch_bounds__(NTHREADS, 1)
lstm_behavior_kernel(const float* __restrict__ x,
                     const float* __restrict__ w_ih0, const float* __restrict__ w_hh0,
                     const float* __restrict__ b_ih0, const float* __restrict__ b_hh0,
                     const float* __restrict__ w_ih1, const float* __restrict__ w_hh1,
                     const float* __restrict__ b_ih1, const float* __restrict__ b_hh1,
                     const float* __restrict__ eng_w1, const float* __restrict__ eng_b1,
                     const float* __restrict__ eng_w2, const float* __restrict__ eng_b2,
                     const float* __restrict__ prop_w1, const float* __restrict__ prop_b1,
                     const float* __restrict__ prop_w2, const float* __restrict__ prop_b2,
                     const float* __restrict__ seg_w, const float* __restrict__ seg_b,
                     float* __restrict__ out, int Btot) {
    extern __shared__ float smf[];
    float* W0  = smf;                       // [64][256] w_hh0, k-major, permuted
    float* W1i = W0  + HID * GATES;         // [64][256] w_ih1
    float* W1h = W1i + HID * GATES;         // [64][256] w_hh1
    float* HA  = W1h + HID * GATES;         // [28][64] layer0 h
    float* HB  = HA  + BTILE * HID;         // [28][64] layer1 h
    float* XS  = HB  + BTILE * HID;         // [2][4][35] x staging, double-buffered

    const int tid = threadIdx.x;

    // ---- prologue: load + permute recurrent weights into SMEM ----
    for (int idx = tid; idx < HID * GATES; idx += NTHREADS) {
        int g = idx >> 6, k = idx & 63;
        int p = permg(g);
        W0 [k * GATES + p] = w_hh0[idx];
        W1i[k * GATES + p] = w_ih1[idx];
        W1h[k * GATES + p] = w_hh1[idx];
    }
    for (int idx = tid; idx < BTILE * HID; idx += NTHREADS) {
        HA[idx] = 0.0f;
        HB[idx] = 0.0f;
    }

    const int w    = tid >> 5;
    const int lane = tid & 31;
    const int bg   = w >> 1;          // batch group 0..3 (7 batches each)
    const int ch   = w & 1;           // cell half
    const int C    = ch * 32 + lane;  // my cell 0..63
    const int b0   = bg * BPG;
    const int plid = ch * 32 + lane;  // pair-local tid 0..63
    const int barid = bg + 1;

    // ---- per-thread register-resident weights: WX (w_ih0) and biases ----
    float4 wxr[F_IN];
    #pragma unroll
    for (int f = 0; f < F_IN; f++) {
        wxr[f].x = w_ih0[(0 * HID + C) * F_IN + f];
        wxr[f].y = w_ih0[(1 * HID + C) * F_IN + f];
        wxr[f].z = w_ih0[(2 * HID + C) * F_IN + f];
        wxr[f].w = w_ih0[(3 * HID + C) * F_IN + f];
    }
    ull b0if = pk2(b_ih0[C] + b_hh0[C],             b_ih0[HID + C] + b_hh0[HID + C]);
    ull b0go = pk2(b_ih0[2 * HID + C] + b_hh0[2 * HID + C],
                   b_ih0[3 * HID + C] + b_hh0[3 * HID + C]);
    ull b1if = pk2(b_ih1[C] + b_hh1[C],             b_ih1[HID + C] + b_hh1[HID + C]);
    ull b1go = pk2(b_ih1[2 * HID + C] + b_hh1[2 * HID + C],
                   b_ih1[3 * HID + C] + b_hh1[3 * HID + C]);

    // ---- x staging setup (clamped for the remainder CTA) ----
    const bool xload = (plid < BPG * F_IN);            // plid < 35
    const int  xb = plid / F_IN, xf = plid - xb * F_IN;
    int gxb = blockIdx.x * BTILE + b0 + xb;
    if (gxb > Btot - 1) gxb = Btot - 1;
    const float* xrow = x + (size_t)gxb * (S_LEN * F_IN) + xf;
    float* xs0 = XS + bg * (BPG * F_IN);               // parity-0 slot for my group
    float* xs1 = XS + (GPB + bg) * (BPG * F_IN);       // parity-1 slot
    const float* xsr0 = xs0;
    const float* xsr1 = xs1;

    float xreg = 0.0f;
    if (xload) {
        xs0[plid] = xrow[0];       // stage t=0
        xreg = xrow[F_IN];         // prefetch t=1
    }

    float cA[BPG], cB[BPG];
    #pragma unroll
    for (int b = 0; b < BPG; b++) { cA[b] = 0.0f; cB[b] = 0.0f; }

    __syncthreads();   // weights + HA/HB zero + XS(0) visible

    for (int t = 0; t < S_LEN; ++t) {
        const float* xcur = (t & 1) ? xsr1 : xsr0;

        // ===== layer 0: gates = B0 + x*W_ih0 + hA(t-1)*W_hh0 =====
        ull acc[BPG][2];
        #pragma unroll
        for (int b = 0; b < BPG; b++) { acc[b][0] = b0if; acc[b][1] = b0go; }
        #pragma unroll
        for (int f = 0; f < F_IN; ++f) {
            ull wif = pk2(wxr[f].x, wxr[f].y);
            ull wgo = pk2(wxr[f].z, wxr[f].w);
            #pragma unroll
            for (int b = 0; b < BPG; b++) {
                ull xv = dup2(xcur[b * F_IN + f]);
                fma2(acc[b][0], wif, xv);
                fma2(acc[b][1], wgo, xv);
            }
        }
        gemm7(HA, W0, C, b0, acc);

        float hn[BPG];
        #pragma unroll
        for (int b = 0; b < BPG; b++)
            hn[b] = cell_update(acc[b][0], acc[b][1], cA[b]);

        BARP(barid);                         // pair done reading HA(t-1)
        #pragma unroll
        for (int b = 0; b < BPG; b++)
            HA[(b0 + b) * HID + C] = hn[b];
        BARP(barid);                         // HA(t) visible

        // ===== layer 1: gates = B1 + hA(t)*W_ih1 + hB(t-1)*W_hh1 =====
        #pragma unroll
        for (int b = 0; b < BPG; b++) { acc[b][0] = b1if; acc[b][1] = b1go; }
        gemm7(HA, W1i, C, b0, acc);
        gemm7(HB, W1h, C, b0, acc);

        // stage x(t+1) into the other parity buffer; prefetch x(t+2)
        if (xload) {
            float* xnxt = (t & 1) ? xs0 : xs1;
            xnxt[plid] = xreg;
            int tn = (t + 2 < S_LEN) ? (t + 2) : (S_LEN - 1);
            xreg = xrow[tn * F_IN];
        }

        #pragma unroll
        for (int b = 0; b < BPG; b++)
            hn[b] = cell_update(acc[b][0], acc[b][1], cB[b]);

        BARP(barid);                         // HB(t-1) reads done; XS(t+1) visible
        #pragma unroll
        for (int b = 0; b < BPG; b++)
            HB[(b0 + b) * HID + C] = hn[b];
        // HB(t) visibility: next iteration's first BARP (after layer0)
    }
    __syncthreads();   // final HB visible block-wide

    // ---- heads: one thread per batch element of this tile ----
    if (tid < BTILE) {
        int b = blockIdx.x * BTILE + tid;
        if (b < Btot) {
            const float* hb = HB + tid * HID;
            out[b]        = mlp_head(hb, eng_w1, eng_b1, eng_w2, eng_b2);
            out[Btot + b] = mlp_head(hb, prop_w1, prop_b1, prop_w2, prop_b2);
            #pragma unroll
            for (int j = 0; j < 5; j++) {
                float s = seg_b[j];
                #pragma unroll 8
                for (int k = 0; k < HID; k++) s += hb[k] * seg_w[j * HID + k];
                out[2 * Btot + b * 5 + j] = s;
            }
        }
    }
}

extern "C" void kernel_launch(void* const* d_in, const int* in_sizes, int n_in,
                              void* d_out, int out_size) {
    const float* x       = (const float*)d_in[0];
    const float* w_ih0   = (const float*)d_in[1];
    const float* w_hh0   = (const float*)d_in[2];
    const float* b_ih0   = (const float*)d_in[3];
    const float* b_hh0   = (const float*)d_in[4];
    const float* w_ih1   = (const float*)d_in[5];
    const float* w_hh1   = (const float*)d_in[6];
    const float* b_ih1   = (const float*)d_in[7];
    const float* b_hh1   = (const float*)d_in[8];
    const float* eng_w1  = (const float*)d_in[9];
    const float* eng_b1  = (const float*)d_in[10];
    const float* eng_w2  = (const float*)d_in[11];
    const float* eng_b2  = (const float*)d_in[12];
    const float* prop_w1 = (const float*)d_in[13];
    const float* prop_b1 = (const float*)d_in[14];
    const float* prop_w2 = (const float*)d_in[15];
    const float* prop_b2 = (const float*)d_in[16];
    const float* seg_w   = (const float*)d_in[17];
    const float* seg_b   = (const float*)d_in[18];
    float* out = (float*)d_out;

    int Btot = in_sizes[0] / (S_LEN * F_IN);        // 4096
    int grid = (Btot + BTILE - 1) / BTILE;          // 147

    size_t smem = (size_t)(3 * HID * GATES + 2 * BTILE * HID +
                           2 * GPB * BPG * F_IN) * sizeof(float);   // 212,064 B
    cudaFuncSetAttribute(lstm_behavior_kernel,
                         cudaFuncAttributeMaxDynamicSharedMemorySize, (int)smem);

    lstm_behavior_kernel<<<grid, NTHREADS, smem>>>(
        x, w_ih0, w_hh0, b_ih0, b_hh0, w_ih1, w_hh1, b_ih1, b_hh1,
        eng_w1, eng_b1, eng_w2, eng_b2, prop_w1, prop_b1, prop_w2, prop_b2,
        seg_w, seg_b, out, Btot);
}